// round 1
// baseline (speedup 1.0000x reference)
#include <cuda_runtime.h>
#include <math.h>

#define NN 50000
#define RR 6
#define EE 32768
#define HH 256
#define FF 16
#define KV 272
#define NHD 8
#define HDD 32
#define RH 1536

// ---------------- scratch (device globals; no runtime allocation) ----------------
__device__ float g_kvin[EE * KV];          // [E, 272] concat(x[src], edge_attr)
__device__ float g_xd[EE * HH];            // [E, 256] x[dst]
__device__ float g_qe[EE * HH];
__device__ float g_k[EE * HH];
__device__ float g_v[EE * HH];
__device__ float g_sc[EE * NHD];           // scores, then exp(scores - m)
__device__ float g_m[NN * NHD];            // segment max
__device__ float g_denom[NN * NHD];        // segment sum of exp
__device__ float g_agg[NN * HH];           // attention aggregate
__device__ float g_relout[NN * RH];        // rel_out in [N, R*H] layout
__device__ float g_hbuf[NN * HH];          // h, later reused for "combined"
__device__ float g_interw[NN * NHD];       // inter-relation softmax weights (6 used)
__device__ float g_cat[NN * 2 * HH];       // [inter_agg | meta]
__device__ float g_paths[3 * NN * HH];     // [3][N][256]
__device__ float g_stacked[NN * 3 * HH];   // [N, 3*256]
__device__ float g_t[3 * NN * (HH / 2)];   // tanh(stacked@Wa1+ba1), [3N,128]

// ---------------- helpers ----------------
__device__ __forceinline__ void atomicMaxF(float* addr, float v) {
    int* ai = (int*)addr;
    int old = *ai;
    while (__int_as_float(old) < v) {
        int assumed = old;
        old = atomicCAS(ai, assumed, __float_as_int(v));
        if (old == assumed) break;
    }
}

__device__ __forceinline__ float gelu_exact(float x) {
    return 0.5f * x * (1.0f + erff(x * 0.7071067811865475f));
}

// ---------------- generic tiled SGEMM: C[m, coff+n] = act(A@B + bias) ----------------
// A: [M,K] row-major stride lda. B: [K,Ncol] row-major. K must be a multiple of 16.
template <int ACT>  // 0=none 1=gelu 2=tanh
__global__ __launch_bounds__(256) void sgemm(const float* __restrict__ A,
                                             const float* __restrict__ B,
                                             const float* __restrict__ bias,
                                             float* __restrict__ C,
                                             int M, int K, int Ncol,
                                             int lda, int ldc, int coff) {
    __shared__ float As[16][68];
    __shared__ float Bs[16][64];
    const int tid = threadIdx.x;
    const int tx = tid & 15, ty = tid >> 4;
    const int bx = blockIdx.x, by = blockIdx.y;

    float acc[4][4] = {};

    for (int k0 = 0; k0 < K; k0 += 16) {
#pragma unroll
        for (int i = 0; i < 4; i++) {
            int idx = tid + 256 * i;
            int ar = idx >> 4, ak = idx & 15;
            int rg = by * 64 + ar;
            As[ak][ar] = (rg < M) ? A[(size_t)rg * lda + k0 + ak] : 0.f;
            int bk = idx >> 6, bc = idx & 63;
            int cg = bx * 64 + bc;
            Bs[bk][bc] = (cg < Ncol) ? B[(size_t)(k0 + bk) * Ncol + cg] : 0.f;
        }
        __syncthreads();
#pragma unroll
        for (int kk = 0; kk < 16; kk++) {
            float a0 = As[kk][ty * 4 + 0];
            float a1 = As[kk][ty * 4 + 1];
            float a2 = As[kk][ty * 4 + 2];
            float a3 = As[kk][ty * 4 + 3];
            float4 b4 = *(const float4*)&Bs[kk][tx * 4];
            acc[0][0] += a0 * b4.x; acc[0][1] += a0 * b4.y; acc[0][2] += a0 * b4.z; acc[0][3] += a0 * b4.w;
            acc[1][0] += a1 * b4.x; acc[1][1] += a1 * b4.y; acc[1][2] += a1 * b4.z; acc[1][3] += a1 * b4.w;
            acc[2][0] += a2 * b4.x; acc[2][1] += a2 * b4.y; acc[2][2] += a2 * b4.z; acc[2][3] += a2 * b4.w;
            acc[3][0] += a3 * b4.x; acc[3][1] += a3 * b4.y; acc[3][2] += a3 * b4.z; acc[3][3] += a3 * b4.w;
        }
        __syncthreads();
    }

#pragma unroll
    for (int i = 0; i < 4; i++) {
        int rg = by * 64 + ty * 4 + i;
        if (rg >= M) continue;
#pragma unroll
        for (int j = 0; j < 4; j++) {
            int cg = bx * 64 + tx * 4 + j;
            if (cg >= Ncol) continue;
            float vv = acc[i][j] + bias[cg];
            if (ACT == 1) vv = gelu_exact(vv);
            else if (ACT == 2) vv = tanhf(vv);
            C[(size_t)rg * ldc + coff + cg] = vv;
        }
    }
}

// ---------------- small kernels ----------------
__global__ void fill_kernel(float* p, int n, float v) {
    int i = blockIdx.x * blockDim.x + threadIdx.x;
    if (i < n) p[i] = v;
}

__global__ void gather_edges(const float* __restrict__ x, const int* __restrict__ ei,
                             const float* __restrict__ ea, int r) {
    int idx = blockIdx.x * blockDim.x + threadIdx.x;
    const int tot1 = EE * KV;
    if (idx < tot1) {
        int e = idx / KV, c = idx - e * KV;
        int src = ei[(r * 2 + 0) * EE + e];
        g_kvin[idx] = (c < HH) ? x[src * HH + c] : ea[((size_t)r * EE + e) * FF + (c - HH)];
    } else {
        int j = idx - tot1;
        if (j < EE * HH) {
            int e = j >> 8, c = j & 255;
            int dst = ei[(r * 2 + 1) * EE + e];
            g_xd[j] = x[dst * HH + c];
        }
    }
}

__global__ void scores_kernel(const int* __restrict__ ei, const float* __restrict__ prior, int r) {
    int idx = blockIdx.x * blockDim.x + threadIdx.x;
    if (idx >= EE * NHD) return;
    int e = idx >> 3, h = idx & 7;
    const float* qp = g_qe + e * HH + h * HDD;
    const float* kp = g_k + e * HH + h * HDD;
    float s = 0.f;
#pragma unroll
    for (int d = 0; d < HDD; d++) s += qp[d] * kp[d];
    s *= 0.17677669529663687f * prior[r * NHD + h];  // 1/sqrt(32) * prior
    g_sc[idx] = s;
    int dst = ei[(r * 2 + 1) * EE + e];
    atomicMaxF(&g_m[dst * NHD + h], s);
}

__global__ void ex_kernel(const int* __restrict__ ei, int r) {
    int idx = blockIdx.x * blockDim.x + threadIdx.x;
    if (idx >= EE * NHD) return;
    int e = idx >> 3, h = idx & 7;
    int dst = ei[(r * 2 + 1) * EE + e];
    float exv = expf(g_sc[idx] - g_m[dst * NHD + h]);
    g_sc[idx] = exv;
    atomicAdd(&g_denom[dst * NHD + h], exv);
}

__global__ void agg_kernel(const int* __restrict__ ei, int r) {
    int idx = blockIdx.x * blockDim.x + threadIdx.x;
    if (idx >= EE * HH) return;
    int e = idx >> 8, c = idx & 255;
    int h = c >> 5;
    int dst = ei[(r * 2 + 1) * EE + e];
    float w = g_sc[e * NHD + h] / (g_denom[dst * NHD + h] + 1e-16f);
    atomicAdd(&g_agg[dst * HH + c], w * g_v[idx]);
}

// one warp per node: logits = h @ W_ir2 + b_ir2, softmax over 6
__global__ void interw_kernel(const float* __restrict__ Wir2, const float* __restrict__ bir2) {
    int gwarp = (blockIdx.x * blockDim.x + threadIdx.x) >> 5;
    int lane = threadIdx.x & 31;
    if (gwarp >= NN) return;
    float acc[RR] = {};
    for (int k = lane; k < HH; k += 32) {
        float hv = g_hbuf[gwarp * HH + k];
#pragma unroll
        for (int rr = 0; rr < RR; rr++) acc[rr] += hv * Wir2[k * RR + rr];
    }
#pragma unroll
    for (int rr = 0; rr < RR; rr++)
#pragma unroll
        for (int off = 16; off; off >>= 1)
            acc[rr] += __shfl_down_sync(0xffffffff, acc[rr], off);
    if (lane == 0) {
        float mx = -1e30f;
#pragma unroll
        for (int rr = 0; rr < RR; rr++) { acc[rr] += bir2[rr]; mx = fmaxf(mx, acc[rr]); }
        float s = 0.f;
#pragma unroll
        for (int rr = 0; rr < RR; rr++) { acc[rr] = expf(acc[rr] - mx); s += acc[rr]; }
        float inv = 1.f / s;
#pragma unroll
        for (int rr = 0; rr < RR; rr++) g_interw[gwarp * NHD + rr] = acc[rr] * inv;
    }
}

__global__ void interagg_kernel() {
    int idx = blockIdx.x * blockDim.x + threadIdx.x;
    if (idx >= NN * HH) return;
    int n = idx >> 8, c = idx & 255;
    const float* ro = g_relout + (size_t)n * RH;
    float s = 0.f;
#pragma unroll
    for (int rr = 0; rr < RR; rr++) s += g_interw[n * NHD + rr] * ro[rr * HH + c];
    g_cat[(size_t)n * 2 * HH + c] = s;
}

__global__ void paths_kernel() {
    int idx = blockIdx.x * blockDim.x + threadIdx.x;
    if (idx >= NN * HH) return;
    int n = idx >> 8, c = idx & 255;
    const float* ro = g_relout + (size_t)n * RH;
    g_paths[(size_t)(0 * NN + n) * HH + c] = ro[2 * HH + c] + ro[3 * HH + c];
    g_paths[(size_t)(1 * NN + n) * HH + c] = ro[4 * HH + c] + ro[0 * HH + c];
    g_paths[(size_t)(2 * NN + n) * HH + c] = ro[1 * HH + c] + ro[5 * HH + c];
}

// block per node: attention over 3 paths + LayerNorm -> g_cat[:,256:512]
__global__ void attnmeta_kernel(const float* __restrict__ Wa2,
                                const float* __restrict__ gm, const float* __restrict__ bm_) {
    __shared__ float lg[3];
    __shared__ float rbuf[256];
    int n = blockIdx.x, t = threadIdx.x;
    int lane = t & 31, w = t >> 5;
    if (w < 3) {
        float a = 0.f;
        for (int j = lane; j < 128; j += 32)
            a += g_t[((size_t)n * 3 + w) * 128 + j] * Wa2[j];
#pragma unroll
        for (int off = 16; off; off >>= 1) a += __shfl_down_sync(0xffffffff, a, off);
        if (lane == 0) lg[w] = a;
    }
    __syncthreads();
    float l0 = lg[0], l1 = lg[1], l2 = lg[2];
    float mx = fmaxf(l0, fmaxf(l1, l2));
    float e0 = expf(l0 - mx), e1 = expf(l1 - mx), e2 = expf(l2 - mx);
    float inv = 1.f / (e0 + e1 + e2);
    const float* st = g_stacked + (size_t)n * 3 * HH;
    float s = (e0 * st[t] + e1 * st[HH + t] + e2 * st[2 * HH + t]) * inv;
    rbuf[t] = s;
    __syncthreads();
    for (int off = 128; off; off >>= 1) { if (t < off) rbuf[t] += rbuf[t + off]; __syncthreads(); }
    float mu = rbuf[0] * (1.f / 256.f);
    __syncthreads();
    float d = s - mu;
    rbuf[t] = d * d;
    __syncthreads();
    for (int off = 128; off; off >>= 1) { if (t < off) rbuf[t] += rbuf[t + off]; __syncthreads(); }
    float var = rbuf[0] * (1.f / 256.f);
    g_cat[(size_t)n * 2 * HH + HH + t] = d * rsqrtf(var + 1e-5f) * gm[t] + bm_[t];
}

// block per node: out = LN(x + combined)
__global__ void outln_kernel(const float* __restrict__ x, const float* __restrict__ gout,
                             const float* __restrict__ bout, float* __restrict__ out) {
    __shared__ float rbuf[256];
    int n = blockIdx.x, t = threadIdx.x;
    float v = x[(size_t)n * HH + t] + g_hbuf[(size_t)n * HH + t];
    rbuf[t] = v;
    __syncthreads();
    for (int off = 128; off; off >>= 1) { if (t < off) rbuf[t] += rbuf[t + off]; __syncthreads(); }
    float mu = rbuf[0] * (1.f / 256.f);
    __syncthreads();
    float d = v - mu;
    rbuf[t] = d * d;
    __syncthreads();
    for (int off = 128; off; off >>= 1) { if (t < off) rbuf[t] += rbuf[t + off]; __syncthreads(); }
    float var = rbuf[0] * (1.f / 256.f);
    out[(size_t)n * HH + t] = d * rsqrtf(var + 1e-5f) * gout[t] + bout[t];
}

// ---------------- host ----------------
static float* symaddr(const void* sym) {
    void* p = nullptr;
    cudaGetSymbolAddress(&p, sym);
    return (float*)p;
}

extern "C" void kernel_launch(void* const* d_in, const int* in_sizes, int n_in,
                              void* d_out, int out_size) {
    const float* x      = (const float*)d_in[0];
    const int*   ei     = (const int*)d_in[1];
    const float* ea     = (const float*)d_in[2];
    const float* Wq     = (const float*)d_in[3];
    const float* bq     = (const float*)d_in[4];
    const float* Wk     = (const float*)d_in[5];
    const float* bk     = (const float*)d_in[6];
    const float* Wv     = (const float*)d_in[7];
    const float* bv     = (const float*)d_in[8];
    const float* prior  = (const float*)d_in[9];
    const float* Wm     = (const float*)d_in[10];
    const float* bm     = (const float*)d_in[11];
    const float* W_ir1  = (const float*)d_in[12];
    const float* b_ir1  = (const float*)d_in[13];
    const float* W_ir2  = (const float*)d_in[14];
    const float* b_ir2  = (const float*)d_in[15];
    const float* Wmp    = (const float*)d_in[16];
    const float* bmp    = (const float*)d_in[17];
    const float* Wa1    = (const float*)d_in[18];
    const float* ba1    = (const float*)d_in[19];
    const float* Wa2    = (const float*)d_in[20];
    const float* gmeta  = (const float*)d_in[21];
    const float* bmeta  = (const float*)d_in[22];
    const float* Wc     = (const float*)d_in[23];
    const float* bc     = (const float*)d_in[24];
    const float* gout   = (const float*)d_in[25];
    const float* bout   = (const float*)d_in[26];
    float* out = (float*)d_out;

    float* p_kvin   = symaddr(g_kvin);
    float* p_xd     = symaddr(g_xd);
    float* p_qe     = symaddr(g_qe);
    float* p_k      = symaddr(g_k);
    float* p_v      = symaddr(g_v);
    float* p_m      = symaddr(g_m);
    float* p_denom  = symaddr(g_denom);
    float* p_agg    = symaddr(g_agg);
    float* p_relout = symaddr(g_relout);
    float* p_hbuf   = symaddr(g_hbuf);
    float* p_cat    = symaddr(g_cat);
    float* p_paths  = symaddr(g_paths);
    float* p_stack  = symaddr(g_stacked);
    float* p_t      = symaddr(g_t);

    const int TB = 256;
    dim3 gE(4, EE / 64);                 // [E,256] output tiles
    dim3 gN(4, (NN + 63) / 64);          // [N,256]
    dim3 g3N(2, (3 * NN + 63) / 64);     // [3N,128]

    for (int r = 0; r < RR; r++) {
        fill_kernel<<<(NN * NHD + TB - 1) / TB, TB>>>(p_m, NN * NHD, -INFINITY);
        fill_kernel<<<(NN * NHD + TB - 1) / TB, TB>>>(p_denom, NN * NHD, 0.f);
        fill_kernel<<<(NN * HH + TB - 1) / TB, TB>>>(p_agg, NN * HH, 0.f);
        gather_edges<<<(EE * (KV + HH) + TB - 1) / TB, TB>>>(x, ei, ea, r);
        sgemm<0><<<gE, TB>>>(p_xd,   Wq + (size_t)r * HH * HH, bq + r * HH, p_qe, EE, HH, HH, HH, HH, 0);
        sgemm<0><<<gE, TB>>>(p_kvin, Wk + (size_t)r * KV * HH, bk + r * HH, p_k,  EE, KV, HH, KV, HH, 0);
        sgemm<0><<<gE, TB>>>(p_kvin, Wv + (size_t)r * KV * HH, bv + r * HH, p_v,  EE, KV, HH, KV, HH, 0);
        scores_kernel<<<EE * NHD / TB, TB>>>(ei, prior, r);
        ex_kernel<<<EE * NHD / TB, TB>>>(ei, r);
        agg_kernel<<<EE * HH / TB, TB>>>(ei, r);
        sgemm<1><<<gN, TB>>>(p_agg, Wm + (size_t)r * HH * HH, bm + r * HH, p_relout,
                             NN, HH, HH, HH, RH, r * HH);
    }

    // inter-relation attention
    sgemm<1><<<gN, TB>>>(p_relout, W_ir1, b_ir1, p_hbuf, NN, RH, HH, RH, HH, 0);
    interw_kernel<<<(NN * 32 + TB - 1) / TB, TB>>>(W_ir2, b_ir2);
    interagg_kernel<<<(NN * HH + TB - 1) / TB, TB>>>();

    // meta paths
    paths_kernel<<<(NN * HH + TB - 1) / TB, TB>>>();
    for (int p = 0; p < 3; p++)
        sgemm<0><<<gN, TB>>>(p_paths + (size_t)p * NN * HH, Wmp + (size_t)p * HH * HH,
                             bmp + p * HH, p_stack, NN, HH, HH, HH, 3 * HH, p * HH);
    sgemm<2><<<g3N, TB>>>(p_stack, Wa1, ba1, p_t, 3 * NN, HH, HH / 2, HH, HH / 2, 0);
    attnmeta_kernel<<<NN, TB>>>(Wa2, gmeta, bmeta);

    // combine + output LN
    sgemm<1><<<gN, TB>>>(p_cat, Wc, bc, p_hbuf, NN, 2 * HH, HH, 2 * HH, HH, 0);
    outln_kernel<<<NN, TB>>>(x, gout, bout, out);
}